// round 5
// baseline (speedup 1.0000x reference)
#include <cuda_runtime.h>

// SPD identity-pad (p=1):
//   x  : [B=8, C=16, H=256, W=256, 3, 3] fp32
//   out: [B, C, 258, 258, 3, 3]          fp32
// Border cells (i==0||i==257||j==0||j==257) = eye(3); interior = x shifted by 1.
//
// Flattened view:
//   out row (bc, i) = 258*9 = 2322 floats, row stride ROW_OUT
//   in  row (bc, i) = 256*9 = 2304 floats, row stride ROW_IN
// Interior of an interior out-row is out[9 .. 2313) = in row (bc, i-1) verbatim.

namespace {
constexpr int H       = 256;
constexpr int HO      = 258;
constexpr int ROW_IN  = 256 * 9;          // 2304
constexpr int ROW_OUT = 258 * 9;          // 2322
constexpr int BC      = 8 * 16;           // 128
constexpr int N_OUT   = BC * HO * ROW_OUT; // 76,681,728  (< 2^31)
}

__global__ void __launch_bounds__(256)
spd_pad_kernel(const float* __restrict__ x, float* __restrict__ out)
{
    int o = blockIdx.x * 256 + threadIdx.x;
    if (o >= N_OUT) return;

    // o -> (row, t);  row -> (bc, i)
    int row = o / ROW_OUT;            // magic-mul
    int t   = o - row * ROW_OUT;      // 0..2321
    int bc  = row / HO;               // magic-mul
    int i   = row - bc * HO;          // 0..257

    float v;
    // interior iff 1 <= i <= 256  AND  9 <= t < 2313
    if ((unsigned)(i - 1) < (unsigned)H && (unsigned)(t - 9) < (unsigned)ROW_IN) {
        v = __ldg(&x[(bc * H + (i - 1)) * ROW_IN + (t - 9)]);
    } else {
        // eye(3) flattened: positions 0,4,8 within each 9-float cell are 1
        int r9 = t % 9;
        v = ((r9 & 3) == 0 && r9 != 0) || r9 == 0 ? 1.0f : 0.0f; // r9 in {0,4,8}
        v = ((r9 % 4) == 0) ? 1.0f : 0.0f;
    }
    out[o] = v;
}

extern "C" void kernel_launch(void* const* d_in, const int* in_sizes, int n_in,
                              void* d_out, int out_size)
{
    const float* x = (const float*)d_in[0];
    float* out = (float*)d_out;
    int blocks = (N_OUT + 255) / 256;   // 299,538
    spd_pad_kernel<<<blocks, 256>>>(x, out);
}

// round 6
// speedup vs baseline: 2.3488x; 2.3488x over previous
#include <cuda_runtime.h>

// SPD identity-pad (p=1):
//   x  : [B=8, C=16, H=256, W=256, 3, 3] fp32  -> flat [BC=128][256][2304]
//   out: [B, C, 258, 258, 3, 3]          fp32  -> flat [BC=128][258][2322]
// Border cells (i==0||257 || j==0||257) = eye(3); interior = x shifted by 1 row/col.
//
// ILP strategy: thread computes (bc_local in [0,16), i, t) once; handles the
// same (i,t) in 8 bc-groups (bc = bc_local + 16*k). Interior predicate depends
// only on (i,t) -> one branch, 8 independent LDGs, 8 coalesced STGs.

namespace {
constexpr int H        = 256;
constexpr int HO       = 258;
constexpr int ROW_IN   = 256 * 9;             // 2304
constexpr int ROW_OUT  = 258 * 9;             // 2322
constexpr int GROUPS   = 8;                   // ILP factor
constexpr int BC_G     = 128 / GROUPS;        // 16 bc per group
constexpr int N_G      = BC_G * HO * ROW_OUT; // 9,585,216 elems per group
constexpr int STRIDE_I = BC_G * H  * ROW_IN;  // in-group stride  = 9,437,184
constexpr int STRIDE_O = N_G;                 // out-group stride = 9,585,216
}

__global__ void __launch_bounds__(256)
spd_pad_ilp8_kernel(const float* __restrict__ x, float* __restrict__ out)
{
    int o = blockIdx.x * 256 + threadIdx.x;
    if (o >= N_G) return;

    // o -> (row, t);  row -> (bc_local, i)   [two magic-mul chains total]
    int row = o / ROW_OUT;
    int t   = o - row * ROW_OUT;      // 0..2321
    int bcl = row / HO;               // 0..15
    int i   = row - bcl * HO;         // 0..257

    // interior iff 1 <= i <= 256  AND  9 <= t < 2313  (same for all 8 groups)
    bool interior = ((unsigned)(i - 1) < (unsigned)H) &&
                    ((unsigned)(t - 9) < (unsigned)ROW_IN);

    if (interior) {
        int src = (bcl * H + (i - 1)) * ROW_IN + (t - 9);
        float v0 = __ldg(x + src + 0 * STRIDE_I);
        float v1 = __ldg(x + src + 1 * STRIDE_I);
        float v2 = __ldg(x + src + 2 * STRIDE_I);
        float v3 = __ldg(x + src + 3 * STRIDE_I);
        float v4 = __ldg(x + src + 4 * STRIDE_I);
        float v5 = __ldg(x + src + 5 * STRIDE_I);
        float v6 = __ldg(x + src + 6 * STRIDE_I);
        float v7 = __ldg(x + src + 7 * STRIDE_I);
        out[o + 0 * STRIDE_O] = v0;
        out[o + 1 * STRIDE_O] = v1;
        out[o + 2 * STRIDE_O] = v2;
        out[o + 3 * STRIDE_O] = v3;
        out[o + 4 * STRIDE_O] = v4;
        out[o + 5 * STRIDE_O] = v5;
        out[o + 6 * STRIDE_O] = v6;
        out[o + 7 * STRIDE_O] = v7;
    } else {
        // eye(3) flattened: positions {0,4,8} within each 9-float cell are 1
        int r9 = t % 9;
        float vb = ((r9 & 3) == 0 || r9 == 8) ? ((r9 % 4) == 0 ? 1.0f : 0.0f)
                                              : 0.0f;
        vb = ((r9 % 4) == 0) ? 1.0f : 0.0f;   // r9 in {0,4,8} -> 1
        #pragma unroll
        for (int k = 0; k < GROUPS; k++)
            out[o + k * STRIDE_O] = vb;
    }
}

extern "C" void kernel_launch(void* const* d_in, const int* in_sizes, int n_in,
                              void* d_out, int out_size)
{
    const float* x = (const float*)d_in[0];
    float* out = (float*)d_out;
    int blocks = (N_G + 255) / 256;   // 37,442
    spd_pad_ilp8_kernel<<<blocks, 256>>>(x, out);
}